// round 2
// baseline (speedup 1.0000x reference)
#include <cuda_runtime.h>
#include <cuda_bf16.h>
#include <stdint.h>
#include <math_constants.h>

#define B_  256
#define C_  345
#define D_  512
#define N_  50000
#define KN  5
#define NV  (N_ + B_)          /* bank cols + 256 virtual f_norm cols */
#define BM  128
#define BN  128
#define BK  32
#define NT  393                /* ceil(NV / BN) */
#define NPAD (NT * BN)         /* 50304 */

/* ---------------- device scratch (static allocation only) ---------------- */
__device__ __align__(16) float          g_p[B_ * C_];        // softmax_out
__device__ float                        g_rowsq[B_];         // ||p_b||^2
__device__ __align__(16) float          g_fn[B_ * D_];       // f_norm fp32
__device__ __align__(16) __nv_bfloat16  g_fnb[B_ * D_];      // f_norm bf16 (GEMM A)
__device__ int                          g_owner[N_];         // scatter owner LUT
__device__ __align__(16) float          g_dist[(size_t)B_ * NPAD];   // 51.5 MB
__device__ int                          g_idx[B_ * KN];      // idx_near
__device__ float                        g_lossparts[B_];
__device__ float                        g_q[C_];             // sum over batch of softmax rows

__device__ __forceinline__ int clampN(int n) {
  return (n < 0) ? 0 : ((n >= N_) ? (N_ - 1) : n);
}

/* ---------------- tiny prep kernels ---------------- */
__global__ void init_owner_k() {
  int i = blockIdx.x * blockDim.x + threadIdx.x;
  if (i < N_) g_owner[i] = -1;
}

__global__ void scatter_owner_k(const int* __restrict__ trg) {
  int b = threadIdx.x;
  atomicMax(&g_owner[clampN(trg[b])], b);   // last-write-wins (max batch idx)
}

__global__ void softmax_k(const float* __restrict__ pred) {
  int b = blockIdx.x, t = threadIdx.x;
  __shared__ float red[128];
  const float* row = pred + (size_t)b * C_;
  float mx = -CUDART_INF_F;
  for (int c = t; c < C_; c += 128) mx = fmaxf(mx, row[c]);
  red[t] = mx; __syncthreads();
  for (int s = 64; s > 0; s >>= 1) { if (t < s) red[t] = fmaxf(red[t], red[t + s]); __syncthreads(); }
  mx = red[0]; __syncthreads();
  float sm = 0.f;
  for (int c = t; c < C_; c += 128) sm += expf(row[c] - mx);
  red[t] = sm; __syncthreads();
  for (int s = 64; s > 0; s >>= 1) { if (t < s) red[t] += red[t + s]; __syncthreads(); }
  float inv = 1.f / red[0]; __syncthreads();
  float sq = 0.f;
  for (int c = t; c < C_; c += 128) {
    float v = expf(row[c] - mx) * inv;
    g_p[(size_t)b * C_ + c] = v;
    sq += v * v;
  }
  red[t] = sq; __syncthreads();
  for (int s = 64; s > 0; s >>= 1) { if (t < s) red[t] += red[t + s]; __syncthreads(); }
  if (t == 0) g_rowsq[b] = red[0];
}

__global__ void fnorm_k(const float* __restrict__ feat) {
  int b = blockIdx.x, t = threadIdx.x;
  __shared__ float red[128];
  const float* row = feat + (size_t)b * D_;
  float sq = 0.f;
  for (int c = t; c < D_; c += 128) { float v = row[c]; sq += v * v; }
  red[t] = sq; __syncthreads();
  for (int s = 64; s > 0; s >>= 1) { if (t < s) red[t] += red[t + s]; __syncthreads(); }
  float inv = 1.f / fmaxf(sqrtf(red[0]), 1e-12f);
  for (int c = t; c < D_; c += 128) {
    float v = row[c] * inv;
    g_fn[(size_t)b * D_ + c]  = v;
    g_fnb[(size_t)b * D_ + c] = __float2bfloat16(v);
  }
}

/* ---------------- bf16 mma.sync GEMM: dist = f_norm @ [fea_bank | f_norm]^T --------------- */
__global__ void __launch_bounds__(256) gemm_k(const float* __restrict__ fb) {
  __shared__ __align__(16) __nv_bfloat16 sA[2][BM][40];   // BK=32 padded to 40
  __shared__ __align__(16) __nv_bfloat16 sB[2][BN][40];

  const int tid  = threadIdx.x;
  const int lane = tid & 31;
  const int warp = tid >> 5;
  const int wm   = warp >> 2;      // 0..1  (64 rows each)
  const int wn   = warp & 3;       // 0..3  (32 cols each)
  const int mBase = blockIdx.y * BM;
  const int nBase = blockIdx.x * BN;

  float acc[4][4][4];
#pragma unroll
  for (int i = 0; i < 4; i++)
#pragma unroll
    for (int j = 0; j < 4; j++)
#pragma unroll
      for (int k = 0; k < 4; k++) acc[i][j][k] = 0.f;

  uint4  aS[2];
  float4 bS[4];

  /* ---- stage 0 global load ---- */
  {
    const int k0 = 0;
#pragma unroll
    for (int t = 0; t < 2; t++) {
      int idx = tid + t * 256, m = idx >> 2, kc = idx & 3;
      aS[t] = *(const uint4*)(g_fnb + (size_t)(mBase + m) * D_ + k0 + kc * 8);
    }
#pragma unroll
    for (int t = 0; t < 4; t++) {
      int idx = tid + t * 256, n = idx >> 3, kc = idx & 7;
      int g = nBase + n;
      const float* src;
      if (g < N_) src = fb + (size_t)g * D_;
      else { int j = g - N_; if (j > B_ - 1) j = B_ - 1; src = g_fn + (size_t)j * D_; }
      bS[t] = *(const float4*)(src + k0 + kc * 4);
    }
  }
  /* stage 0 store to smem buf 0 */
#pragma unroll
  for (int t = 0; t < 2; t++) {
    int idx = tid + t * 256, m = idx >> 2, kc = idx & 3;
    *(uint4*)&sA[0][m][kc * 8] = aS[t];
  }
#pragma unroll
  for (int t = 0; t < 4; t++) {
    int idx = tid + t * 256, n = idx >> 3, kc = idx & 7;
    __nv_bfloat162 lo = __floats2bfloat162_rn(bS[t].x, bS[t].y);
    __nv_bfloat162 hi = __floats2bfloat162_rn(bS[t].z, bS[t].w);
    uint2 v; v.x = *(uint32_t*)&lo; v.y = *(uint32_t*)&hi;
    *(uint2*)&sB[0][n][kc * 4] = v;
  }
  __syncthreads();

#pragma unroll 1
  for (int kt = 0; kt < 16; kt++) {
    const int buf = kt & 1;
    /* prefetch next tile into registers */
    if (kt + 1 < 16) {
      const int k0 = (kt + 1) * BK;
#pragma unroll
      for (int t = 0; t < 2; t++) {
        int idx = tid + t * 256, m = idx >> 2, kc = idx & 3;
        aS[t] = *(const uint4*)(g_fnb + (size_t)(mBase + m) * D_ + k0 + kc * 8);
      }
#pragma unroll
      for (int t = 0; t < 4; t++) {
        int idx = tid + t * 256, n = idx >> 3, kc = idx & 7;
        int g = nBase + n;
        const float* src;
        if (g < N_) src = fb + (size_t)g * D_;
        else { int j = g - N_; if (j > B_ - 1) j = B_ - 1; src = g_fn + (size_t)j * D_; }
        bS[t] = *(const float4*)(src + k0 + kc * 4);
      }
    }
    /* compute on buf */
#pragma unroll
    for (int ks = 0; ks < 2; ks++) {
      const int kk = ks * 16 + (lane & 3) * 2;
      uint32_t af[4][4], bfr[4][2];
#pragma unroll
      for (int mi = 0; mi < 4; mi++) {
        int r = wm * 64 + mi * 16 + (lane >> 2);
        af[mi][0] = *(const uint32_t*)&sA[buf][r][kk];
        af[mi][1] = *(const uint32_t*)&sA[buf][r + 8][kk];
        af[mi][2] = *(const uint32_t*)&sA[buf][r][kk + 8];
        af[mi][3] = *(const uint32_t*)&sA[buf][r + 8][kk + 8];
      }
#pragma unroll
      for (int ni = 0; ni < 4; ni++) {
        int n = wn * 32 + ni * 8 + (lane >> 2);
        bfr[ni][0] = *(const uint32_t*)&sB[buf][n][kk];
        bfr[ni][1] = *(const uint32_t*)&sB[buf][n][kk + 8];
      }
#pragma unroll
      for (int mi = 0; mi < 4; mi++)
#pragma unroll
        for (int ni = 0; ni < 4; ni++)
          asm volatile(
            "mma.sync.aligned.m16n8k16.row.col.f32.bf16.bf16.f32 "
            "{%0,%1,%2,%3}, {%4,%5,%6,%7}, {%8,%9}, {%0,%1,%2,%3};\n"
            : "+f"(acc[mi][ni][0]), "+f"(acc[mi][ni][1]),
              "+f"(acc[mi][ni][2]), "+f"(acc[mi][ni][3])
            : "r"(af[mi][0]), "r"(af[mi][1]), "r"(af[mi][2]), "r"(af[mi][3]),
              "r"(bfr[ni][0]), "r"(bfr[ni][1]));
    }
    /* store prefetched tile into other buffer */
    if (kt + 1 < 16) {
      const int nb = (kt + 1) & 1;
#pragma unroll
      for (int t = 0; t < 2; t++) {
        int idx = tid + t * 256, m = idx >> 2, kc = idx & 3;
        *(uint4*)&sA[nb][m][kc * 8] = aS[t];
      }
#pragma unroll
      for (int t = 0; t < 4; t++) {
        int idx = tid + t * 256, n = idx >> 3, kc = idx & 7;
        __nv_bfloat162 lo = __floats2bfloat162_rn(bS[t].x, bS[t].y);
        __nv_bfloat162 hi = __floats2bfloat162_rn(bS[t].z, bS[t].w);
        uint2 v; v.x = *(uint32_t*)&lo; v.y = *(uint32_t*)&hi;
        *(uint2*)&sB[nb][n][kc * 4] = v;
      }
      __syncthreads();
    }
  }

  /* epilogue: grid exactly covers [256, NPAD] -> no guards */
#pragma unroll
  for (int mi = 0; mi < 4; mi++) {
    int r = mBase + wm * 64 + mi * 16 + (lane >> 2);
#pragma unroll
    for (int ni = 0; ni < 4; ni++) {
      int cb = nBase + wn * 32 + ni * 8 + (lane & 3) * 2;
      float2 v0 = make_float2(acc[mi][ni][0], acc[mi][ni][1]);
      float2 v1 = make_float2(acc[mi][ni][2], acc[mi][ni][3]);
      *(float2*)&g_dist[(size_t)r * NPAD + cb]       = v0;
      *(float2*)&g_dist[(size_t)(r + 8) * NPAD + cb] = v1;
    }
  }
}

/* ---------------- scatter fixup: overwrite scattered columns with virtual cols ----------- */
__global__ void fixup_k(const int* __restrict__ trg) {
  int j = blockIdx.x;
  int n = clampN(trg[j]);
  if (g_owner[n] != j) return;       // dedup: only the winning owner writes
  int b = threadIdx.x;
  g_dist[(size_t)b * NPAD + n] = g_dist[(size_t)b * NPAD + N_ + j];
}

/* ---------------- top-6 per row, drop rank-0, keep idx 1..5 ---------------- */
__device__ __forceinline__ bool betterf(float v, int i, float v2, int i2) {
  return (v > v2) || (v == v2 && i < i2);
}

__global__ void topk_k() {
  const int b = blockIdx.x, t = threadIdx.x;
  __shared__ float sv[256 * 6];
  __shared__ int   si[256 * 6];

  float bv[6]; int bi[6];
#pragma unroll
  for (int j = 0; j < 6; j++) { bv[j] = -CUDART_INF_F; bi[j] = 0x7fffffff; }

  const float* row = g_dist + (size_t)b * NPAD;
  for (int c4 = t; c4 < N_ / 4; c4 += 256) {
    float4 d = *(const float4*)(row + c4 * 4);
    float vv[4] = {d.x, d.y, d.z, d.w};
#pragma unroll
    for (int u = 0; u < 4; u++) {
      float val = vv[u]; int id = c4 * 4 + u;
      if (betterf(val, id, bv[5], bi[5])) {
        bv[5] = val; bi[5] = id;
#pragma unroll
        for (int j = 5; j > 0; j--) {
          if (betterf(bv[j], bi[j], bv[j - 1], bi[j - 1])) {
            float tv = bv[j]; bv[j] = bv[j - 1]; bv[j - 1] = tv;
            int  ti = bi[j]; bi[j] = bi[j - 1]; bi[j - 1] = ti;
          }
        }
      }
    }
  }
#pragma unroll
  for (int j = 0; j < 6; j++) { sv[t * 6 + j] = bv[j]; si[t * 6 + j] = bi[j]; }
  __syncthreads();

  if (t < 32) {
    float mv[6]; int mi_[6];
#pragma unroll
    for (int j = 0; j < 6; j++) { mv[j] = -CUDART_INF_F; mi_[j] = 0x7fffffff; }
    for (int src = t; src < 256; src += 32) {
      for (int j = 0; j < 6; j++) {
        float val = sv[src * 6 + j]; int id = si[src * 6 + j];
        if (betterf(val, id, mv[5], mi_[5])) {
          mv[5] = val; mi_[5] = id;
#pragma unroll
          for (int q = 5; q > 0; q--) {
            if (betterf(mv[q], mi_[q], mv[q - 1], mi_[q - 1])) {
              float tv = mv[q]; mv[q] = mv[q - 1]; mv[q - 1] = tv;
              int  ti = mi_[q]; mi_[q] = mi_[q - 1]; mi_[q - 1] = ti;
            }
          }
        }
      }
    }
#pragma unroll
    for (int j = 0; j < 6; j++) { sv[t * 6 + j] = mv[j]; si[t * 6 + j] = mi_[j]; }
  }
  __syncthreads();

  if (t == 0) {
    float mv[6]; int mi_[6];
#pragma unroll
    for (int j = 0; j < 6; j++) { mv[j] = -CUDART_INF_F; mi_[j] = 0x7fffffff; }
    for (int src = 0; src < 32; src++) {
      for (int j = 0; j < 6; j++) {
        float val = sv[src * 6 + j]; int id = si[src * 6 + j];
        if (betterf(val, id, mv[5], mi_[5])) {
          mv[5] = val; mi_[5] = id;
#pragma unroll
          for (int q = 5; q > 0; q--) {
            if (betterf(mv[q], mi_[q], mv[q - 1], mi_[q - 1])) {
              float tv = mv[q]; mv[q] = mv[q - 1]; mv[q - 1] = tv;
              int  ti = mi_[q]; mi_[q] = mi_[q - 1]; mi_[q - 1] = ti;
            }
          }
        }
      }
    }
#pragma unroll
    for (int j = 1; j < 6; j++) g_idx[b * KN + (j - 1)] = mi_[j];   // drop rank-0
  }
}

/* ---------------- KL term per batch row ---------------- */
__global__ void kl_k(const float* __restrict__ sb) {
  const int b = blockIdx.x, t = threadIdx.x;
  __shared__ float red[128];
  float acc = 0.f;
  for (int k = 0; k < KN; k++) {
    int n  = g_idx[b * KN + k];
    int ow = g_owner[n];
    const float* srow = (ow >= 0) ? (g_p + (size_t)ow * C_)
                                  : (sb + (size_t)n * C_);
    for (int c = t; c < C_; c += 128) {
      float s = srow[c];
      acc += s * (logf(s) - g_p[(size_t)b * C_ + c]);
    }
  }
  red[t] = acc; __syncthreads();
  for (int s = 64; s > 0; s >>= 1) { if (t < s) red[t] += red[t + s]; __syncthreads(); }
  if (t == 0) g_lossparts[b] = red[0];
}

/* ---------------- q = sum_b softmax rows ---------------- */
__global__ void colsum_k() {
  int c = threadIdx.x;
  if (c < C_) {
    float s = 0.f;
    for (int b = 0; b < B_; b++) s += g_p[(size_t)b * C_ + c];
    g_q[c] = s;
  }
}

/* ---------------- final scalar: loss = mean(kl) + (||q||^2 - sum rowsq)/B -------------- */
__global__ void final_k(float* __restrict__ out) {
  __shared__ float r1[512], r2[512], r3[512];
  int t = threadIdx.x;
  float a = 0.f, q2 = 0.f, rr = 0.f;
  if (t < B_) { a = g_lossparts[t]; rr = g_rowsq[t]; }
  for (int c = t; c < C_; c += 512) { float q = g_q[c]; q2 += q * q; }
  r1[t] = a; r2[t] = q2; r3[t] = rr; __syncthreads();
  for (int s = 256; s > 0; s >>= 1) {
    if (t < s) { r1[t] += r1[t + s]; r2[t] += r2[t + s]; r3[t] += r3[t + s]; }
    __syncthreads();
  }
  if (t == 0) out[0] = r1[0] / (float)B_ + 1.0f * ((r2[0] - r3[0]) / (float)B_);
}

/* ---------------- launch ---------------- */
extern "C" void kernel_launch(void* const* d_in, const int* in_sizes, int n_in,
                              void* d_out, int out_size) {
  (void)in_sizes; (void)n_in; (void)out_size;
  const float* feat = (const float*)d_in[0];
  const float* pred = (const float*)d_in[1];
  const float* fb   = (const float*)d_in[2];
  const float* sb   = (const float*)d_in[3];
  const int*   trg  = (const int*)d_in[4];   /* JAX x64 disabled -> int32 */

  init_owner_k<<<(N_ + 1023) / 1024, 1024>>>();
  scatter_owner_k<<<1, B_>>>(trg);
  softmax_k<<<B_, 128>>>(pred);
  fnorm_k<<<B_, 128>>>(feat);
  dim3 g(NT, 2);
  gemm_k<<<g, 256>>>(fb);
  fixup_k<<<B_, B_>>>(trg);
  topk_k<<<B_, 256>>>();
  kl_k<<<B_, 128>>>(sb);
  colsum_k<<<1, 384>>>();
  final_k<<<1, 512>>>((float*)d_out);
}